// round 13
// baseline (speedup 1.0000x reference)
#include <cuda_runtime.h>
#include <cuda_fp16.h>

#define N_ITEMS 100000
#define KNN_K   5
#define VEC     32                 // 32 float4 (or uint2) per 128-elem row
#define WARPS_PER_BLOCK 8
#define THREADS (WARPS_PER_BLOCK * 32)
#define PAIRS   (N_ITEMS / 2)      // 50000 row-pairs, one per warp-iteration
#define MAX_ITERS 6                // supports grid >= ceil(50000/(8*6)) = 1042 blocks

// Layer-1 output in fp16 (25.6 MB) for the cross-row gathers in phase 2.
__device__ uint2 g_x1h[(size_t)N_ITEMS * VEC];
// Monotonic grid-barrier ticket. Each launch consumes exactly gridDim.x
// tickets, so epochs stay aligned across graph replays (no reset needed).
__device__ unsigned g_ticket;

__device__ __forceinline__ void grid_barrier() {
    __syncthreads();
    if (threadIdx.x == 0) {
        __threadfence();                                   // release x1h stores
        unsigned t = atomicAdd(&g_ticket, 1u);
        unsigned target = (t / gridDim.x + 1u) * gridDim.x;
        while (*(volatile unsigned*)&g_ticket < target) __nanosleep(32);
        __threadfence();                                   // acquire
    }
    __syncthreads();
}

// Fused GCN: phase 1 = layer1 (fp32 gathers -> x1h), grid barrier,
// phase 2 = layer2 (fp16 gathers + residual). The warp's own x1 rows and
// indices cross the barrier in SMEM, saving the 26 MB x1h-own re-read and
// one kernel launch. __launch_bounds__(256, 8) guarantees 8 blocks/SM
// (regs capped at 32) so the grid = SMs*8 is fully co-resident (no deadlock).
__global__ __launch_bounds__(THREADS, 8) void gcn_fused(
    const float4* __restrict__ x0,
    const int*    __restrict__ idx,
    float4*       __restrict__ out,
    float c)
{
    __shared__ uint2 s_x1[WARPS_PER_BLOCK][MAX_ITERS][2][32];  // 24576 B
    __shared__ int   s_idx[WARPS_PER_BLOCK][MAX_ITERS][2 * KNN_K]; // 1920 B

    int warp = threadIdx.x >> 5;
    int lane = threadIdx.x & 31;
    int gwarp0 = blockIdx.x * WARPS_PER_BLOCK + warp;
    int warps_total = gridDim.x * WARPS_PER_BLOCK;

    // ---------------- phase 1: x1 = c * A x0 ----------------
    for (int it = 0; it < MAX_ITERS; it++) {
        int pair = it * warps_total + gwarp0;
        if (pair < PAIRS) {
            int row0 = pair * 2;
            int my = 0;
            if (lane < 2 * KNN_K) my = __ldg(idx + row0 * KNN_K + lane);
            if (lane < 2 * KNN_K) s_idx[warp][it][lane] = my;
            int j0 = __shfl_sync(0xffffffffu, my, 0);
            int j1 = __shfl_sync(0xffffffffu, my, 1);
            int j2 = __shfl_sync(0xffffffffu, my, 2);
            int j3 = __shfl_sync(0xffffffffu, my, 3);
            int j4 = __shfl_sync(0xffffffffu, my, 4);
            int j5 = __shfl_sync(0xffffffffu, my, 5);
            int j6 = __shfl_sync(0xffffffffu, my, 6);
            int j7 = __shfl_sync(0xffffffffu, my, 7);
            int j8 = __shfl_sync(0xffffffffu, my, 8);
            int j9 = __shfl_sync(0xffffffffu, my, 9);

            float4 a0 = __ldg(x0 + (size_t)j0 * VEC + lane);
            float4 a1 = __ldg(x0 + (size_t)j1 * VEC + lane);
            float4 a2 = __ldg(x0 + (size_t)j2 * VEC + lane);
            float4 a3 = __ldg(x0 + (size_t)j3 * VEC + lane);
            float4 a4 = __ldg(x0 + (size_t)j4 * VEC + lane);
            float4 b0 = __ldg(x0 + (size_t)j5 * VEC + lane);
            float4 b1 = __ldg(x0 + (size_t)j6 * VEC + lane);
            float4 b2 = __ldg(x0 + (size_t)j7 * VEC + lane);
            float4 b3 = __ldg(x0 + (size_t)j8 * VEC + lane);
            float4 b4 = __ldg(x0 + (size_t)j9 * VEC + lane);

            float4 s0, s1;
            s0.x = c * (a0.x + a1.x + a2.x + a3.x + a4.x);
            s0.y = c * (a0.y + a1.y + a2.y + a3.y + a4.y);
            s0.z = c * (a0.z + a1.z + a2.z + a3.z + a4.z);
            s0.w = c * (a0.w + a1.w + a2.w + a3.w + a4.w);
            s1.x = c * (b0.x + b1.x + b2.x + b3.x + b4.x);
            s1.y = c * (b0.y + b1.y + b2.y + b3.y + b4.y);
            s1.z = c * (b0.z + b1.z + b2.z + b3.z + b4.z);
            s1.w = c * (b0.w + b1.w + b2.w + b3.w + b4.w);

            __half2 h00 = __floats2half2_rn(s0.x, s0.y);
            __half2 h01 = __floats2half2_rn(s0.z, s0.w);
            __half2 h10 = __floats2half2_rn(s1.x, s1.y);
            __half2 h11 = __floats2half2_rn(s1.z, s1.w);
            uint2 u0, u1;
            u0.x = *reinterpret_cast<unsigned int*>(&h00);
            u0.y = *reinterpret_cast<unsigned int*>(&h01);
            u1.x = *reinterpret_cast<unsigned int*>(&h10);
            u1.y = *reinterpret_cast<unsigned int*>(&h11);
            g_x1h[(size_t)row0 * VEC + lane] = u0;
            g_x1h[(size_t)(row0 + 1) * VEC + lane] = u1;
            s_x1[warp][it][0][lane] = u0;      // own x1 crosses the barrier in SMEM
            s_x1[warp][it][1][lane] = u1;
        }
    }

    grid_barrier();

    // -------- phase 2: out = x0 + x1 + c * A x1 --------
    for (int it = 0; it < MAX_ITERS; it++) {
        int pair = it * warps_total + gwarp0;
        if (pair < PAIRS) {
            int row0 = pair * 2;
            int j0 = s_idx[warp][it][0];   // smem broadcast, no idx re-read
            int j1 = s_idx[warp][it][1];
            int j2 = s_idx[warp][it][2];
            int j3 = s_idx[warp][it][3];
            int j4 = s_idx[warp][it][4];
            int j5 = s_idx[warp][it][5];
            int j6 = s_idx[warp][it][6];
            int j7 = s_idx[warp][it][7];
            int j8 = s_idx[warp][it][8];
            int j9 = s_idx[warp][it][9];

            const uint2* x1h = g_x1h;
            uint2 g0 = __ldg(x1h + (size_t)j0 * VEC + lane);
            uint2 g1 = __ldg(x1h + (size_t)j1 * VEC + lane);
            uint2 g2 = __ldg(x1h + (size_t)j2 * VEC + lane);
            uint2 g3 = __ldg(x1h + (size_t)j3 * VEC + lane);
            uint2 g4 = __ldg(x1h + (size_t)j4 * VEC + lane);
            uint2 h0 = __ldg(x1h + (size_t)j5 * VEC + lane);
            uint2 h1 = __ldg(x1h + (size_t)j6 * VEC + lane);
            uint2 h2 = __ldg(x1h + (size_t)j7 * VEC + lane);
            uint2 h3 = __ldg(x1h + (size_t)j8 * VEC + lane);
            uint2 h4 = __ldg(x1h + (size_t)j9 * VEC + lane);
            uint2 gr0 = s_x1[warp][it][0][lane];   // own x1 from SMEM (saves 26 MB)
            uint2 gr1 = s_x1[warp][it][1][lane];
            float4 r00 = __ldcs(x0 + (size_t)row0 * VEC + lane);
            float4 r01 = __ldcs(x0 + (size_t)(row0 + 1) * VEC + lane);

            float2 A0 = __half22float2(*reinterpret_cast<__half2*>(&g0.x));
            float2 A1 = __half22float2(*reinterpret_cast<__half2*>(&g0.y));
            float2 B0 = __half22float2(*reinterpret_cast<__half2*>(&g1.x));
            float2 B1 = __half22float2(*reinterpret_cast<__half2*>(&g1.y));
            float2 C0 = __half22float2(*reinterpret_cast<__half2*>(&g2.x));
            float2 C1 = __half22float2(*reinterpret_cast<__half2*>(&g2.y));
            float2 D0 = __half22float2(*reinterpret_cast<__half2*>(&g3.x));
            float2 D1 = __half22float2(*reinterpret_cast<__half2*>(&g3.y));
            float2 E0 = __half22float2(*reinterpret_cast<__half2*>(&g4.x));
            float2 E1 = __half22float2(*reinterpret_cast<__half2*>(&g4.y));
            float2 R0 = __half22float2(*reinterpret_cast<__half2*>(&gr0.x));
            float2 R1 = __half22float2(*reinterpret_cast<__half2*>(&gr0.y));

            float4 s0;
            s0.x = r00.x + R0.x + c * (A0.x + B0.x + C0.x + D0.x + E0.x);
            s0.y = r00.y + R0.y + c * (A0.y + B0.y + C0.y + D0.y + E0.y);
            s0.z = r00.z + R1.x + c * (A1.x + B1.x + C1.x + D1.x + E1.x);
            s0.w = r00.w + R1.y + c * (A1.y + B1.y + C1.y + D1.y + E1.y);
            __stcs(out + (size_t)row0 * VEC + lane, s0);

            A0 = __half22float2(*reinterpret_cast<__half2*>(&h0.x));
            A1 = __half22float2(*reinterpret_cast<__half2*>(&h0.y));
            B0 = __half22float2(*reinterpret_cast<__half2*>(&h1.x));
            B1 = __half22float2(*reinterpret_cast<__half2*>(&h1.y));
            C0 = __half22float2(*reinterpret_cast<__half2*>(&h2.x));
            C1 = __half22float2(*reinterpret_cast<__half2*>(&h2.y));
            D0 = __half22float2(*reinterpret_cast<__half2*>(&h3.x));
            D1 = __half22float2(*reinterpret_cast<__half2*>(&h3.y));
            E0 = __half22float2(*reinterpret_cast<__half2*>(&h4.x));
            E1 = __half22float2(*reinterpret_cast<__half2*>(&h4.y));
            R0 = __half22float2(*reinterpret_cast<__half2*>(&gr1.x));
            R1 = __half22float2(*reinterpret_cast<__half2*>(&gr1.y));

            float4 s1;
            s1.x = r01.x + R0.x + c * (A0.x + B0.x + C0.x + D0.x + E0.x);
            s1.y = r01.y + R0.y + c * (A0.y + B0.y + C0.y + D0.y + E0.y);
            s1.z = r01.z + R1.x + c * (A1.x + B1.x + C1.x + D1.x + E1.x);
            s1.w = r01.w + R1.y + c * (A1.y + B1.y + C1.y + D1.y + E1.y);
            __stcs(out + (size_t)(row0 + 1) * VEC + lane, s1);
        }
    }
}

// ---------------- fallback (R6 two-kernel path) for small devices ----------
#define FB_BLOCKS (PAIRS / WARPS_PER_BLOCK)

__global__ __launch_bounds__(THREADS) void spmm_layer1(
    const float4* __restrict__ x0, const int* __restrict__ idx, float c)
{
    int warp = blockIdx.x * WARPS_PER_BLOCK + (threadIdx.x >> 5);
    int lane = threadIdx.x & 31;
    int row0 = warp * 2;
    int my = 0;
    if (lane < 2 * KNN_K) my = __ldg(idx + row0 * KNN_K + lane);
    int j0 = __shfl_sync(0xffffffffu, my, 0), j1 = __shfl_sync(0xffffffffu, my, 1);
    int j2 = __shfl_sync(0xffffffffu, my, 2), j3 = __shfl_sync(0xffffffffu, my, 3);
    int j4 = __shfl_sync(0xffffffffu, my, 4), j5 = __shfl_sync(0xffffffffu, my, 5);
    int j6 = __shfl_sync(0xffffffffu, my, 6), j7 = __shfl_sync(0xffffffffu, my, 7);
    int j8 = __shfl_sync(0xffffffffu, my, 8), j9 = __shfl_sync(0xffffffffu, my, 9);
    float4 a0 = __ldg(x0 + (size_t)j0 * VEC + lane), a1 = __ldg(x0 + (size_t)j1 * VEC + lane);
    float4 a2 = __ldg(x0 + (size_t)j2 * VEC + lane), a3 = __ldg(x0 + (size_t)j3 * VEC + lane);
    float4 a4 = __ldg(x0 + (size_t)j4 * VEC + lane), b0 = __ldg(x0 + (size_t)j5 * VEC + lane);
    float4 b1 = __ldg(x0 + (size_t)j6 * VEC + lane), b2 = __ldg(x0 + (size_t)j7 * VEC + lane);
    float4 b3 = __ldg(x0 + (size_t)j8 * VEC + lane), b4 = __ldg(x0 + (size_t)j9 * VEC + lane);
    float4 s0, s1;
    s0.x = c * (a0.x + a1.x + a2.x + a3.x + a4.x);
    s0.y = c * (a0.y + a1.y + a2.y + a3.y + a4.y);
    s0.z = c * (a0.z + a1.z + a2.z + a3.z + a4.z);
    s0.w = c * (a0.w + a1.w + a2.w + a3.w + a4.w);
    s1.x = c * (b0.x + b1.x + b2.x + b3.x + b4.x);
    s1.y = c * (b0.y + b1.y + b2.y + b3.y + b4.y);
    s1.z = c * (b0.z + b1.z + b2.z + b3.z + b4.z);
    s1.w = c * (b0.w + b1.w + b2.w + b3.w + b4.w);
    __half2 h00 = __floats2half2_rn(s0.x, s0.y), h01 = __floats2half2_rn(s0.z, s0.w);
    __half2 h10 = __floats2half2_rn(s1.x, s1.y), h11 = __floats2half2_rn(s1.z, s1.w);
    uint2 u0, u1;
    u0.x = *reinterpret_cast<unsigned int*>(&h00); u0.y = *reinterpret_cast<unsigned int*>(&h01);
    u1.x = *reinterpret_cast<unsigned int*>(&h10); u1.y = *reinterpret_cast<unsigned int*>(&h11);
    g_x1h[(size_t)row0 * VEC + lane] = u0;
    g_x1h[(size_t)(row0 + 1) * VEC + lane] = u1;
}

__global__ __launch_bounds__(THREADS) void spmm_layer2(
    const float4* __restrict__ x0, const int* __restrict__ idx,
    float4* __restrict__ out, float c)
{
    int warp = blockIdx.x * WARPS_PER_BLOCK + (threadIdx.x >> 5);
    int lane = threadIdx.x & 31;
    int row0 = warp * 2;
    int my = 0;
    if (lane < 2 * KNN_K) my = __ldg(idx + row0 * KNN_K + lane);
    int j0 = __shfl_sync(0xffffffffu, my, 0), j1 = __shfl_sync(0xffffffffu, my, 1);
    int j2 = __shfl_sync(0xffffffffu, my, 2), j3 = __shfl_sync(0xffffffffu, my, 3);
    int j4 = __shfl_sync(0xffffffffu, my, 4), j5 = __shfl_sync(0xffffffffu, my, 5);
    int j6 = __shfl_sync(0xffffffffu, my, 6), j7 = __shfl_sync(0xffffffffu, my, 7);
    int j8 = __shfl_sync(0xffffffffu, my, 8), j9 = __shfl_sync(0xffffffffu, my, 9);
    const uint2* x1h = g_x1h;
    uint2 g0 = __ldg(x1h + (size_t)j0 * VEC + lane), g1 = __ldg(x1h + (size_t)j1 * VEC + lane);
    uint2 g2 = __ldg(x1h + (size_t)j2 * VEC + lane), g3 = __ldg(x1h + (size_t)j3 * VEC + lane);
    uint2 g4 = __ldg(x1h + (size_t)j4 * VEC + lane), h0 = __ldg(x1h + (size_t)j5 * VEC + lane);
    uint2 h1 = __ldg(x1h + (size_t)j6 * VEC + lane), h2 = __ldg(x1h + (size_t)j7 * VEC + lane);
    uint2 h3 = __ldg(x1h + (size_t)j8 * VEC + lane), h4 = __ldg(x1h + (size_t)j9 * VEC + lane);
    uint2 gr0 = __ldg(x1h + (size_t)row0 * VEC + lane);
    uint2 gr1 = __ldg(x1h + (size_t)(row0 + 1) * VEC + lane);
    float4 r00 = __ldg(x0 + (size_t)row0 * VEC + lane);
    float4 r01 = __ldg(x0 + (size_t)(row0 + 1) * VEC + lane);
    float2 A0 = __half22float2(*reinterpret_cast<__half2*>(&g0.x));
    float2 A1 = __half22float2(*reinterpret_cast<__half2*>(&g0.y));
    float2 B0 = __half22float2(*reinterpret_cast<__half2*>(&g1.x));
    float2 B1 = __half22float2(*reinterpret_cast<__half2*>(&g1.y));
    float2 C0 = __half22float2(*reinterpret_cast<__half2*>(&g2.x));
    float2 C1 = __half22float2(*reinterpret_cast<__half2*>(&g2.y));
    float2 D0 = __half22float2(*reinterpret_cast<__half2*>(&g3.x));
    float2 D1 = __half22float2(*reinterpret_cast<__half2*>(&g3.y));
    float2 E0 = __half22float2(*reinterpret_cast<__half2*>(&g4.x));
    float2 E1 = __half22float2(*reinterpret_cast<__half2*>(&g4.y));
    float2 R0 = __half22float2(*reinterpret_cast<__half2*>(&gr0.x));
    float2 R1 = __half22float2(*reinterpret_cast<__half2*>(&gr0.y));
    float4 s0;
    s0.x = r00.x + R0.x + c * (A0.x + B0.x + C0.x + D0.x + E0.x);
    s0.y = r00.y + R0.y + c * (A0.y + B0.y + C0.y + D0.y + E0.y);
    s0.z = r00.z + R1.x + c * (A1.x + B1.x + C1.x + D1.x + E1.x);
    s0.w = r00.w + R1.y + c * (A1.y + B1.y + C1.y + D1.y + E1.y);
    __stcs(out + (size_t)row0 * VEC + lane, s0);
    A0 = __half22float2(*reinterpret_cast<__half2*>(&h0.x));
    A1 = __half22float2(*reinterpret_cast<__half2*>(&h0.y));
    B0 = __half22float2(*reinterpret_cast<__half2*>(&h1.x));
    B1 = __half22float2(*reinterpret_cast<__half2*>(&h1.y));
    C0 = __half22float2(*reinterpret_cast<__half2*>(&h2.x));
    C1 = __half22float2(*reinterpret_cast<__half2*>(&h2.y));
    D0 = __half22float2(*reinterpret_cast<__half2*>(&h3.x));
    D1 = __half22float2(*reinterpret_cast<__half2*>(&h3.y));
    E0 = __half22float2(*reinterpret_cast<__half2*>(&h4.x));
    E1 = __half22float2(*reinterpret_cast<__half2*>(&h4.y));
    R0 = __half22float2(*reinterpret_cast<__half2*>(&gr1.x));
    R1 = __half22float2(*reinterpret_cast<__half2*>(&gr1.y));
    float4 s1;
    s1.x = r01.x + R0.x + c * (A0.x + B0.x + C0.x + D0.x + E0.x);
    s1.y = r01.y + R0.y + c * (A0.y + B0.y + C0.y + D0.y + E0.y);
    s1.z = r01.z + R1.x + c * (A1.x + B1.x + C1.x + D1.x + E1.x);
    s1.w = r01.w + R1.y + c * (A1.y + B1.y + C1.y + D1.y + E1.y);
    __stcs(out + (size_t)(row0 + 1) * VEC + lane, s1);
}
// ---------------------------------------------------------------------------

extern "C" void kernel_launch(void* const* d_in, const int* in_sizes, int n_in,
                              void* d_out, int out_size)
{
    const float4* x0  = (const float4*)d_in[0];   // item_rep [N, 128] f32
    const int*    idx = (const int*)d_in[1];      // knn_ind  [N, 5] i32
    float4*       out = (float4*)d_out;

    // vals[n,k] = (K+1e-7)^-0.5 * (K+1e-7)^-0.5 == 1/(K+1e-7): a constant.
    float c = (float)(1.0 / (5.0 + 1e-7));

    int dev = 0, sms = 0;
    cudaGetDevice(&dev);
    cudaDeviceGetAttribute(&sms, cudaDevAttrMultiProcessorCount, dev);
    int grid = sms * 8;   // exactly co-resident under __launch_bounds__(256, 8)

    if ((long long)grid * WARPS_PER_BLOCK * MAX_ITERS >= PAIRS) {
        gcn_fused<<<grid, THREADS>>>(x0, idx, out, c);
    } else {
        // Device too small for the persistent grid: safe two-kernel path.
        spmm_layer1<<<FB_BLOCKS, THREADS>>>(x0, idx, c);
        spmm_layer2<<<FB_BLOCKS, THREADS>>>(x0, idx, out, c);
    }
}

// round 14
// speedup vs baseline: 1.1591x; 1.1591x over previous
#include <cuda_runtime.h>
#include <cuda_fp16.h>

#define N_ITEMS 100000
#define KNN_K   5
#define VEC     32                 // 32 float4 (or uint2) per 128-elem row
#define WARPS_PER_BLOCK 8
#define THREADS (WARPS_PER_BLOCK * 32)
#define PAIRS   (N_ITEMS / 2)      // 50000 row-pairs

// Layer-1 output in fp16 (25.6 MB). Within the fused kernel, x0 (51.2) +
// x1h (25.6) = 77 MB stay L2-resident across the phase boundary; out goes
// write-through so it never allocates (R13 used __stcs -> 128 MB > L2).
__device__ uint2 g_x1h[(size_t)N_ITEMS * VEC];
// Monotonic grid-barrier ticket (each launch consumes exactly gridDim.x).
__device__ unsigned g_ticket;
// Work-steal counters. g_ctr2 is reset by block 0 BEFORE the barrier
// (visible to phase 2 via the barrier's release/acquire); g_ctr1 is reset
// AFTER the barrier (visible to the NEXT launch via stream ordering).
__device__ unsigned g_ctr1;
__device__ unsigned g_ctr2;

__device__ __forceinline__ void grid_barrier() {
    __syncthreads();
    if (threadIdx.x == 0) {
        __threadfence();                                    // release phase-1 stores
        unsigned t = atomicAdd(&g_ticket, 1u);
        unsigned target = (t / gridDim.x + 1u) * gridDim.x;
        while (*(volatile unsigned*)&g_ticket < target) __nanosleep(64);
        __threadfence();                                    // acquire
    }
    __syncthreads();
}

__global__ __launch_bounds__(THREADS, 8) void gcn_fused(
    const float4* __restrict__ x0,
    const int*    __restrict__ idx,
    float4*       __restrict__ out,
    float c)
{
    __shared__ unsigned s_base;
    int warp = threadIdx.x >> 5;
    int lane = threadIdx.x & 31;

    if (blockIdx.x == 0 && threadIdx.x == 0) g_ctr2 = 0;  // for THIS launch's
                                                          // phase 2 (ordered by barrier)

    // ---------------- phase 1: x1 = c * A x0  (work-stealing) ----------------
    for (;;) {
        if (threadIdx.x == 0) s_base = atomicAdd(&g_ctr1, (unsigned)WARPS_PER_BLOCK);
        __syncthreads();
        unsigned base = s_base;
        __syncthreads();
        if (base >= PAIRS) break;
        unsigned pair = base + warp;
        if (pair < PAIRS) {
            int row0 = (int)pair * 2;
            int my = 0;
            if (lane < 2 * KNN_K) my = __ldg(idx + row0 * KNN_K + lane);
            int j0 = __shfl_sync(0xffffffffu, my, 0);
            int j1 = __shfl_sync(0xffffffffu, my, 1);
            int j2 = __shfl_sync(0xffffffffu, my, 2);
            int j3 = __shfl_sync(0xffffffffu, my, 3);
            int j4 = __shfl_sync(0xffffffffu, my, 4);
            int j5 = __shfl_sync(0xffffffffu, my, 5);
            int j6 = __shfl_sync(0xffffffffu, my, 6);
            int j7 = __shfl_sync(0xffffffffu, my, 7);
            int j8 = __shfl_sync(0xffffffffu, my, 8);
            int j9 = __shfl_sync(0xffffffffu, my, 9);

            float4 a0 = __ldg(x0 + (size_t)j0 * VEC + lane);
            float4 a1 = __ldg(x0 + (size_t)j1 * VEC + lane);
            float4 a2 = __ldg(x0 + (size_t)j2 * VEC + lane);
            float4 a3 = __ldg(x0 + (size_t)j3 * VEC + lane);
            float4 a4 = __ldg(x0 + (size_t)j4 * VEC + lane);
            float4 b0 = __ldg(x0 + (size_t)j5 * VEC + lane);
            float4 b1 = __ldg(x0 + (size_t)j6 * VEC + lane);
            float4 b2 = __ldg(x0 + (size_t)j7 * VEC + lane);
            float4 b3 = __ldg(x0 + (size_t)j8 * VEC + lane);
            float4 b4 = __ldg(x0 + (size_t)j9 * VEC + lane);

            float4 s0, s1;
            s0.x = c * (a0.x + a1.x + a2.x + a3.x + a4.x);
            s0.y = c * (a0.y + a1.y + a2.y + a3.y + a4.y);
            s0.z = c * (a0.z + a1.z + a2.z + a3.z + a4.z);
            s0.w = c * (a0.w + a1.w + a2.w + a3.w + a4.w);
            s1.x = c * (b0.x + b1.x + b2.x + b3.x + b4.x);
            s1.y = c * (b0.y + b1.y + b2.y + b3.y + b4.y);
            s1.z = c * (b0.z + b1.z + b2.z + b3.z + b4.z);
            s1.w = c * (b0.w + b1.w + b2.w + b3.w + b4.w);

            __half2 h00 = __floats2half2_rn(s0.x, s0.y);
            __half2 h01 = __floats2half2_rn(s0.z, s0.w);
            __half2 h10 = __floats2half2_rn(s1.x, s1.y);
            __half2 h11 = __floats2half2_rn(s1.z, s1.w);
            uint2 u0, u1;
            u0.x = *reinterpret_cast<unsigned int*>(&h00);
            u0.y = *reinterpret_cast<unsigned int*>(&h01);
            u1.x = *reinterpret_cast<unsigned int*>(&h10);
            u1.y = *reinterpret_cast<unsigned int*>(&h11);
            g_x1h[(size_t)row0 * VEC + lane] = u0;
            g_x1h[(size_t)(row0 + 1) * VEC + lane] = u1;
        }
    }

    grid_barrier();

    if (blockIdx.x == 0 && threadIdx.x == 0) g_ctr1 = 0;  // for the NEXT launch

    // -------- phase 2: out = x0 + x1 + c * A x1  (work-stealing) --------
    for (;;) {
        if (threadIdx.x == 0) s_base = atomicAdd(&g_ctr2, (unsigned)WARPS_PER_BLOCK);
        __syncthreads();
        unsigned base = s_base;
        __syncthreads();
        if (base >= PAIRS) break;
        unsigned pair = base + warp;
        if (pair < PAIRS) {
            int row0 = (int)pair * 2;
            int my = 0;
            if (lane < 2 * KNN_K) my = __ldg(idx + row0 * KNN_K + lane);
            int j0 = __shfl_sync(0xffffffffu, my, 0);
            int j1 = __shfl_sync(0xffffffffu, my, 1);
            int j2 = __shfl_sync(0xffffffffu, my, 2);
            int j3 = __shfl_sync(0xffffffffu, my, 3);
            int j4 = __shfl_sync(0xffffffffu, my, 4);
            int j5 = __shfl_sync(0xffffffffu, my, 5);
            int j6 = __shfl_sync(0xffffffffu, my, 6);
            int j7 = __shfl_sync(0xffffffffu, my, 7);
            int j8 = __shfl_sync(0xffffffffu, my, 8);
            int j9 = __shfl_sync(0xffffffffu, my, 9);

            const uint2* x1h = g_x1h;
            uint2 g0 = __ldg(x1h + (size_t)j0 * VEC + lane);   // L2-hot (written
            uint2 g1 = __ldg(x1h + (size_t)j1 * VEC + lane);   //  this launch)
            uint2 g2 = __ldg(x1h + (size_t)j2 * VEC + lane);
            uint2 g3 = __ldg(x1h + (size_t)j3 * VEC + lane);
            uint2 g4 = __ldg(x1h + (size_t)j4 * VEC + lane);
            uint2 h0 = __ldg(x1h + (size_t)j5 * VEC + lane);
            uint2 h1 = __ldg(x1h + (size_t)j6 * VEC + lane);
            uint2 h2 = __ldg(x1h + (size_t)j7 * VEC + lane);
            uint2 h3 = __ldg(x1h + (size_t)j8 * VEC + lane);
            uint2 h4 = __ldg(x1h + (size_t)j9 * VEC + lane);
            uint2 gr0 = __ldg(x1h + (size_t)row0 * VEC + lane);
            uint2 gr1 = __ldg(x1h + (size_t)(row0 + 1) * VEC + lane);
            float4 r00 = __ldg(x0 + (size_t)row0 * VEC + lane);    // L2-hot from
            float4 r01 = __ldg(x0 + (size_t)(row0 + 1) * VEC + lane); // phase 1

            float2 A0 = __half22float2(*reinterpret_cast<__half2*>(&g0.x));
            float2 A1 = __half22float2(*reinterpret_cast<__half2*>(&g0.y));
            float2 B0 = __half22float2(*reinterpret_cast<__half2*>(&g1.x));
            float2 B1 = __half22float2(*reinterpret_cast<__half2*>(&g1.y));
            float2 C0 = __half22float2(*reinterpret_cast<__half2*>(&g2.x));
            float2 C1 = __half22float2(*reinterpret_cast<__half2*>(&g2.y));
            float2 D0 = __half22float2(*reinterpret_cast<__half2*>(&g3.x));
            float2 D1 = __half22float2(*reinterpret_cast<__half2*>(&g3.y));
            float2 E0 = __half22float2(*reinterpret_cast<__half2*>(&g4.x));
            float2 E1 = __half22float2(*reinterpret_cast<__half2*>(&g4.y));
            float2 R0 = __half22float2(*reinterpret_cast<__half2*>(&gr0.x));
            float2 R1 = __half22float2(*reinterpret_cast<__half2*>(&gr0.y));

            float4 s0;
            s0.x = r00.x + R0.x + c * (A0.x + B0.x + C0.x + D0.x + E0.x);
            s0.y = r00.y + R0.y + c * (A0.y + B0.y + C0.y + D0.y + E0.y);
            s0.z = r00.z + R1.x + c * (A1.x + B1.x + C1.x + D1.x + E1.x);
            s0.w = r00.w + R1.y + c * (A1.y + B1.y + C1.y + D1.y + E1.y);
            __stwt(out + (size_t)row0 * VEC + lane, s0);   // write-through: no L2 alloc

            A0 = __half22float2(*reinterpret_cast<__half2*>(&h0.x));
            A1 = __half22float2(*reinterpret_cast<__half2*>(&h0.y));
            B0 = __half22float2(*reinterpret_cast<__half2*>(&h1.x));
            B1 = __half22float2(*reinterpret_cast<__half2*>(&h1.y));
            C0 = __half22float2(*reinterpret_cast<__half2*>(&h2.x));
            C1 = __half22float2(*reinterpret_cast<__half2*>(&h2.y));
            D0 = __half22float2(*reinterpret_cast<__half2*>(&h3.x));
            D1 = __half22float2(*reinterpret_cast<__half2*>(&h3.y));
            E0 = __half22float2(*reinterpret_cast<__half2*>(&h4.x));
            E1 = __half22float2(*reinterpret_cast<__half2*>(&h4.y));
            R0 = __half22float2(*reinterpret_cast<__half2*>(&gr1.x));
            R1 = __half22float2(*reinterpret_cast<__half2*>(&gr1.y));

            float4 s1;
            s1.x = r01.x + R0.x + c * (A0.x + B0.x + C0.x + D0.x + E0.x);
            s1.y = r01.y + R0.y + c * (A0.y + B0.y + C0.y + D0.y + E0.y);
            s1.z = r01.z + R1.x + c * (A1.x + B1.x + C1.x + D1.x + E1.x);
            s1.w = r01.w + R1.y + c * (A1.y + B1.y + C1.y + D1.y + E1.y);
            __stwt(out + (size_t)(row0 + 1) * VEC + lane, s1);
        }
    }
}

// ---------------- fallback (R6 two-kernel path) -----------------------------
#define FB_BLOCKS (PAIRS / WARPS_PER_BLOCK)

__global__ __launch_bounds__(THREADS) void spmm_layer1(
    const float4* __restrict__ x0, const int* __restrict__ idx, float c)
{
    int warp = blockIdx.x * WARPS_PER_BLOCK + (threadIdx.x >> 5);
    int lane = threadIdx.x & 31;
    int row0 = warp * 2;
    int my = 0;
    if (lane < 2 * KNN_K) my = __ldg(idx + row0 * KNN_K + lane);
    int j0 = __shfl_sync(0xffffffffu, my, 0), j1 = __shfl_sync(0xffffffffu, my, 1);
    int j2 = __shfl_sync(0xffffffffu, my, 2), j3 = __shfl_sync(0xffffffffu, my, 3);
    int j4 = __shfl_sync(0xffffffffu, my, 4), j5 = __shfl_sync(0xffffffffu, my, 5);
    int j6 = __shfl_sync(0xffffffffu, my, 6), j7 = __shfl_sync(0xffffffffu, my, 7);
    int j8 = __shfl_sync(0xffffffffu, my, 8), j9 = __shfl_sync(0xffffffffu, my, 9);
    float4 a0 = __ldg(x0 + (size_t)j0 * VEC + lane), a1 = __ldg(x0 + (size_t)j1 * VEC + lane);
    float4 a2 = __ldg(x0 + (size_t)j2 * VEC + lane), a3 = __ldg(x0 + (size_t)j3 * VEC + lane);
    float4 a4 = __ldg(x0 + (size_t)j4 * VEC + lane), b0 = __ldg(x0 + (size_t)j5 * VEC + lane);
    float4 b1 = __ldg(x0 + (size_t)j6 * VEC + lane), b2 = __ldg(x0 + (size_t)j7 * VEC + lane);
    float4 b3 = __ldg(x0 + (size_t)j8 * VEC + lane), b4 = __ldg(x0 + (size_t)j9 * VEC + lane);
    float4 s0, s1;
    s0.x = c * (a0.x + a1.x + a2.x + a3.x + a4.x);
    s0.y = c * (a0.y + a1.y + a2.y + a3.y + a4.y);
    s0.z = c * (a0.z + a1.z + a2.z + a3.z + a4.z);
    s0.w = c * (a0.w + a1.w + a2.w + a3.w + a4.w);
    s1.x = c * (b0.x + b1.x + b2.x + b3.x + b4.x);
    s1.y = c * (b0.y + b1.y + b2.y + b3.y + b4.y);
    s1.z = c * (b0.z + b1.z + b2.z + b3.z + b4.z);
    s1.w = c * (b0.w + b1.w + b2.w + b3.w + b4.w);
    __half2 h00 = __floats2half2_rn(s0.x, s0.y), h01 = __floats2half2_rn(s0.z, s0.w);
    __half2 h10 = __floats2half2_rn(s1.x, s1.y), h11 = __floats2half2_rn(s1.z, s1.w);
    uint2 u0, u1;
    u0.x = *reinterpret_cast<unsigned int*>(&h00); u0.y = *reinterpret_cast<unsigned int*>(&h01);
    u1.x = *reinterpret_cast<unsigned int*>(&h10); u1.y = *reinterpret_cast<unsigned int*>(&h11);
    g_x1h[(size_t)row0 * VEC + lane] = u0;
    g_x1h[(size_t)(row0 + 1) * VEC + lane] = u1;
}

__global__ __launch_bounds__(THREADS) void spmm_layer2(
    const float4* __restrict__ x0, const int* __restrict__ idx,
    float4* __restrict__ out, float c)
{
    int warp = blockIdx.x * WARPS_PER_BLOCK + (threadIdx.x >> 5);
    int lane = threadIdx.x & 31;
    int row0 = warp * 2;
    int my = 0;
    if (lane < 2 * KNN_K) my = __ldg(idx + row0 * KNN_K + lane);
    int j0 = __shfl_sync(0xffffffffu, my, 0), j1 = __shfl_sync(0xffffffffu, my, 1);
    int j2 = __shfl_sync(0xffffffffu, my, 2), j3 = __shfl_sync(0xffffffffu, my, 3);
    int j4 = __shfl_sync(0xffffffffu, my, 4), j5 = __shfl_sync(0xffffffffu, my, 5);
    int j6 = __shfl_sync(0xffffffffu, my, 6), j7 = __shfl_sync(0xffffffffu, my, 7);
    int j8 = __shfl_sync(0xffffffffu, my, 8), j9 = __shfl_sync(0xffffffffu, my, 9);
    const uint2* x1h = g_x1h;
    uint2 g0 = __ldg(x1h + (size_t)j0 * VEC + lane), g1 = __ldg(x1h + (size_t)j1 * VEC + lane);
    uint2 g2 = __ldg(x1h + (size_t)j2 * VEC + lane), g3 = __ldg(x1h + (size_t)j3 * VEC + lane);
    uint2 g4 = __ldg(x1h + (size_t)j4 * VEC + lane), h0 = __ldg(x1h + (size_t)j5 * VEC + lane);
    uint2 h1 = __ldg(x1h + (size_t)j6 * VEC + lane), h2 = __ldg(x1h + (size_t)j7 * VEC + lane);
    uint2 h3 = __ldg(x1h + (size_t)j8 * VEC + lane), h4 = __ldg(x1h + (size_t)j9 * VEC + lane);
    uint2 gr0 = __ldg(x1h + (size_t)row0 * VEC + lane);
    uint2 gr1 = __ldg(x1h + (size_t)(row0 + 1) * VEC + lane);
    float4 r00 = __ldg(x0 + (size_t)row0 * VEC + lane);
    float4 r01 = __ldg(x0 + (size_t)(row0 + 1) * VEC + lane);
    float2 A0 = __half22float2(*reinterpret_cast<__half2*>(&g0.x));
    float2 A1 = __half22float2(*reinterpret_cast<__half2*>(&g0.y));
    float2 B0 = __half22float2(*reinterpret_cast<__half2*>(&g1.x));
    float2 B1 = __half22float2(*reinterpret_cast<__half2*>(&g1.y));
    float2 C0 = __half22float2(*reinterpret_cast<__half2*>(&g2.x));
    float2 C1 = __half22float2(*reinterpret_cast<__half2*>(&g2.y));
    float2 D0 = __half22float2(*reinterpret_cast<__half2*>(&g3.x));
    float2 D1 = __half22float2(*reinterpret_cast<__half2*>(&g3.y));
    float2 E0 = __half22float2(*reinterpret_cast<__half2*>(&g4.x));
    float2 E1 = __half22float2(*reinterpret_cast<__half2*>(&g4.y));
    float2 R0 = __half22float2(*reinterpret_cast<__half2*>(&gr0.x));
    float2 R1 = __half22float2(*reinterpret_cast<__half2*>(&gr0.y));
    float4 s0;
    s0.x = r00.x + R0.x + c * (A0.x + B0.x + C0.x + D0.x + E0.x);
    s0.y = r00.y + R0.y + c * (A0.y + B0.y + C0.y + D0.y + E0.y);
    s0.z = r00.z + R1.x + c * (A1.x + B1.x + C1.x + D1.x + E1.x);
    s0.w = r00.w + R1.y + c * (A1.y + B1.y + C1.y + D1.y + E1.y);
    __stcs(out + (size_t)row0 * VEC + lane, s0);
    A0 = __half22float2(*reinterpret_cast<__half2*>(&h0.x));
    A1 = __half22float2(*reinterpret_cast<__half2*>(&h0.y));
    B0 = __half22float2(*reinterpret_cast<__half2*>(&h1.x));
    B1 = __half22float2(*reinterpret_cast<__half2*>(&h1.y));
    C0 = __half22float2(*reinterpret_cast<__half2*>(&h2.x));
    C1 = __half22float2(*reinterpret_cast<__half2*>(&h2.y));
    D0 = __half22float2(*reinterpret_cast<__half2*>(&h3.x));
    D1 = __half22float2(*reinterpret_cast<__half2*>(&h3.y));
    E0 = __half22float2(*reinterpret_cast<__half2*>(&h4.x));
    E1 = __half22float2(*reinterpret_cast<__half2*>(&h4.y));
    R0 = __half22float2(*reinterpret_cast<__half2*>(&gr1.x));
    R1 = __half22float2(*reinterpret_cast<__half2*>(&gr1.y));
    float4 s1;
    s1.x = r01.x + R0.x + c * (A0.x + B0.x + C0.x + D0.x + E0.x);
    s1.y = r01.y + R0.y + c * (A0.y + B0.y + C0.y + D0.y + E0.y);
    s1.z = r01.z + R1.x + c * (A1.x + B1.x + C1.x + D1.x + E1.x);
    s1.w = r01.w + R1.y + c * (A1.y + B1.y + C1.y + D1.y + E1.y);
    __stcs(out + (size_t)(row0 + 1) * VEC + lane, s1);
}
// ---------------------------------------------------------------------------

extern "C" void kernel_launch(void* const* d_in, const int* in_sizes, int n_in,
                              void* d_out, int out_size)
{
    const float4* x0  = (const float4*)d_in[0];   // item_rep [N, 128] f32
    const int*    idx = (const int*)d_in[1];      // knn_ind  [N, 5] i32
    float4*       out = (float4*)d_out;

    // vals[n,k] = (K+1e-7)^-0.5 * (K+1e-7)^-0.5 == 1/(K+1e-7): a constant.
    float c = (float)(1.0 / (5.0 + 1e-7));

    int dev = 0, sms = 0;
    cudaGetDevice(&dev);
    cudaDeviceGetAttribute(&sms, cudaDevAttrMultiProcessorCount, dev);

    if (sms > 0) {
        int grid = sms * 8;   // exactly co-resident under __launch_bounds__(256, 8)
        gcn_fused<<<grid, THREADS>>>(x0, idx, out, c);
    } else {
        spmm_layer1<<<FB_BLOCKS, THREADS>>>(x0, idx, c);
        spmm_layer2<<<FB_BLOCKS, THREADS>>>(x0, idx, out, c);
    }
}